// round 1
// baseline (speedup 1.0000x reference)
#include <cuda_runtime.h>
#include <math.h>

#define LDQ 512
#define LSK 2048
#define CS  384
#define CH  16
#define NH  12
#define PQ  4
#define PV  8
#define TI  8

// ---------------- scratch (no allocations allowed) ----------------
__device__ float g_q[LDQ*NH*CH];                 // 512 x 192
__device__ float g_qp_raw[LDQ*NH*PQ*3];          // 512 x 144
__device__ float g_qp[LDQ*NH*PQ*3];              // (i,h,p,c)
__device__ float g_kv[LSK*NH*2*CH];              // 2048 x 384  (k|v interleaved per head)
__device__ float g_kvp_raw[LSK*NH*(PQ+PV)*3];    // 2048 x 432
__device__ float g_kpts[LSK*NH*PQ*3];            // (j,h,p,c)
__device__ float g_vpts[LSK*NH*PV*3];            // (j,h,p,c)
__device__ float g_cat[LDQ*576];                 // concat features

// ---------------- generic tiled GEMM: C[MxN] = A[MxK] @ B[KxN] (+bias) ----------------
__global__ __launch_bounds__(256) void gemm_bias(
    const float* __restrict__ A, const float* __restrict__ Bm,
    float* __restrict__ C, int M, int N, int K, const float* __restrict__ bias)
{
    __shared__ float As[16][65];
    __shared__ float Bs[16][64];
    const int t  = threadIdx.x;
    const int tx = t & 15, ty = t >> 4;
    const int rowBase = blockIdx.y * 64;
    const int colBase = blockIdx.x * 64;
    float acc[4][4] = {};

    for (int kt = 0; kt < K; kt += 16) {
#pragma unroll
        for (int u = 0; u < 4; u++) {
            int idx = t + 256*u;            // 0..1023
            int m = idx >> 4, k = idx & 15;
            int gm = rowBase + m;
            As[k][m] = (gm < M) ? A[(long long)gm*K + kt + k] : 0.f;
        }
#pragma unroll
        for (int u = 0; u < 4; u++) {
            int idx = t + 256*u;
            int k = idx >> 6, n = idx & 63;
            int gn = colBase + n;
            Bs[k][n] = (gn < N) ? Bm[(long long)(kt+k)*N + gn] : 0.f;
        }
        __syncthreads();
#pragma unroll
        for (int kk = 0; kk < 16; kk++) {
            float a0[4], b0[4];
#pragma unroll
            for (int i = 0; i < 4; i++) a0[i] = As[kk][ty*4+i];
#pragma unroll
            for (int j = 0; j < 4; j++) b0[j] = Bs[kk][tx*4+j];
#pragma unroll
            for (int i = 0; i < 4; i++)
#pragma unroll
                for (int j = 0; j < 4; j++)
                    acc[i][j] = fmaf(a0[i], b0[j], acc[i][j]);
        }
        __syncthreads();
    }
#pragma unroll
    for (int i = 0; i < 4; i++) {
        int gm = rowBase + ty*4 + i;
        if (gm >= M) continue;
#pragma unroll
        for (int j = 0; j < 4; j++) {
            int gn = colBase + tx*4 + j;
            if (gn < N) C[(long long)gm*N + gn] = acc[i][j] + (bias ? bias[gn] : 0.f);
        }
    }
}

// ---------------- apply frames ----------------
// qp_raw layout per row i (144): col = c*48 + pidx, pidx = h*4 + p
__global__ void rot_dst_kernel(const float* __restrict__ R, const float* __restrict__ t) {
    int idx = blockIdx.x*256 + threadIdx.x;
    if (idx >= LDQ*48) return;
    int i = idx / 48, pidx = idx - (idx/48)*48;
    float l0 = g_qp_raw[i*144 + pidx];
    float l1 = g_qp_raw[i*144 + 48 + pidx];
    float l2 = g_qp_raw[i*144 + 96 + pidx];
    const float* Ri = R + i*9;
    const float* ti = t + i*3;
    g_qp[i*144 + pidx*3 + 0] = Ri[0]*l0 + Ri[1]*l1 + Ri[2]*l2 + ti[0];
    g_qp[i*144 + pidx*3 + 1] = Ri[3]*l0 + Ri[4]*l1 + Ri[5]*l2 + ti[1];
    g_qp[i*144 + pidx*3 + 2] = Ri[6]*l0 + Ri[7]*l1 + Ri[8]*l2 + ti[2];
}

// kvp_raw per row j (432): col = c*144 + pidx, pidx = h*12 + pp (pp<4: k_pts, else v_pts)
__global__ void rot_src_kernel(const float* __restrict__ R, const float* __restrict__ t) {
    int idx = blockIdx.x*256 + threadIdx.x;
    if (idx >= LSK*144) return;
    int j = idx / 144, pidx = idx - (idx/144)*144;
    float l0 = g_kvp_raw[j*432 + pidx];
    float l1 = g_kvp_raw[j*432 + 144 + pidx];
    float l2 = g_kvp_raw[j*432 + 288 + pidx];
    const float* Rj = R + j*9;
    const float* tj = t + j*3;
    float g0 = Rj[0]*l0 + Rj[1]*l1 + Rj[2]*l2 + tj[0];
    float g1 = Rj[3]*l0 + Rj[4]*l1 + Rj[5]*l2 + tj[1];
    float g2 = Rj[6]*l0 + Rj[7]*l1 + Rj[8]*l2 + tj[2];
    int h = pidx / 12, pp = pidx - h*12;
    if (pp < 4) {
        float* d = &g_kpts[j*144 + h*12 + pp*3];
        d[0] = g0; d[1] = g1; d[2] = g2;
    } else {
        float* d = &g_vpts[j*288 + h*24 + (pp-4)*3];
        d[0] = g0; d[1] = g1; d[2] = g2;
    }
}

// ---------------- attention: block = (head h, 8 query rows); warp r owns row i0+r ----------------
__global__ __launch_bounds__(256) void attn_kernel(
    const float* __restrict__ dst_mask, const float* __restrict__ src_mask,
    const float* __restrict__ R_dst, const float* __restrict__ t_dst,
    const float* __restrict__ head_w,
    float* __restrict__ a_out, float* __restrict__ asd_out, float* __restrict__ apts_out)
{
    extern __shared__ float sh[];
    float*  probs = sh;                           // TI * LSK
    float*  ktile = sh + TI*LSK;                  // 64 rows x stride 30 (16 k + 12 kpts)
    float2* vtile = (float2*)(sh + TI*LSK);       // 64 rows x stride 33 float2 (dims lane, lane+32)
    __shared__ float optbuf[TI][24];

    const int h    = blockIdx.x;
    const int t    = threadIdx.x;
    const int warp = t >> 5, lane = t & 31;
    const int i    = blockIdx.y*TI + warp;

    float qv[CH], qpv[12];
#pragma unroll
    for (int c = 0; c < CH; c++) qv[c]  = g_q[i*(NH*CH) + h*CH + c];
#pragma unroll
    for (int c = 0; c < 12; c++) qpv[c] = g_qp[i*144 + h*12 + c];
    const float dm   = dst_mask[i];
    const float hwv  = log1pf(__expf(head_w[h])) * (1.0f/6.0f);     // softplus * sqrt(1/36)
    const float qksc = 0.17677669529663689f;                        // 1/sqrt(2*C_H)
    const long long rowoff = (long long)(h*LDQ + i) * LSK;
    float* prow = probs + warp*LSK;

    // ---- pass 1: logits + a_sd + a_pts ----
    for (int jt = 0; jt < LSK; jt += 64) {
        for (int idx = t; idx < 64*28; idx += 256) {
            int j2 = idx / 28, c = idx - j2*28;
            int j = jt + j2;
            float v = (c < 16) ? g_kv[j*384 + h*32 + c]
                               : g_kpts[j*144 + h*12 + (c-16)];
            ktile[j2*30 + c] = v;
        }
        __syncthreads();
#pragma unroll
        for (int u = 0; u < 2; u++) {
            int j2 = lane + 32*u;
            int j  = jt + j2;
            const float2* T2 = (const float2*)(ktile + j2*30);
            float qk = 0.f, s2 = 0.f;
#pragma unroll
            for (int c = 0; c < 8; c++) {
                float2 kk = T2[c];
                qk = fmaf(qv[2*c], kk.x, qk);
                qk = fmaf(qv[2*c+1], kk.y, qk);
            }
#pragma unroll
            for (int c = 0; c < 6; c++) {
                float2 kk = T2[8+c];
                float d0 = qpv[2*c]   - kk.x;
                float d1 = qpv[2*c+1] - kk.y;
                s2 = fmaf(d0, d0, s2);
                s2 = fmaf(d1, d1, s2);
            }
            float ptatt = -0.5f * hwv * s2;
            float g  = dm * src_mask[j];
            float as = qk * qksc;
            asd_out[rowoff + j]  = as * g;
            apts_out[rowoff + j] = ptatt * g;
            prow[j] = as + ptatt + 1e9f*(g - 1.0f);   // sq_mask = INF*(g-1)
        }
        __syncthreads();
    }

    // ---- softmax per warp over own row ----
    float m = -3.0e38f;
    for (int j = lane; j < LSK; j += 32) m = fmaxf(m, prow[j]);
#pragma unroll
    for (int o = 16; o; o >>= 1) m = fmaxf(m, __shfl_xor_sync(0xffffffffu, m, o));
    float s = 0.f;
    for (int j = lane; j < LSK; j += 32) { float e = __expf(prow[j] - m); prow[j] = e; s += e; }
#pragma unroll
    for (int o = 16; o; o >>= 1) s += __shfl_xor_sync(0xffffffffu, s, o);
    float inv = 1.f / s;
    for (int j = lane; j < LSK; j += 32) { float p = prow[j]*inv; prow[j] = p; a_out[rowoff + j] = p; }

    // ---- pass 2: o (16) + o_pt (24) ; lane owns dim=lane (and 32+lane for lane<8) ----
    float acc0 = 0.f, acc1 = 0.f;
    for (int jt = 0; jt < LSK; jt += 64) {
        for (int idx = t; idx < 64*32; idx += 256) {
            int j2 = idx >> 5, d = idx & 31;
            int j = jt + j2;
            float x = (d < 16) ? g_kv[j*384 + h*32 + 16 + d]
                               : g_vpts[j*288 + h*24 + (d-16)];
            float y = (d < 8) ? g_vpts[j*288 + h*24 + (16+d)] : 0.f;
            vtile[j2*33 + d] = make_float2(x, y);
        }
        __syncthreads();
#pragma unroll 4
        for (int j2 = 0; j2 < 64; j2++) {
            float  p  = prow[jt + j2];
            float2 vv = vtile[j2*33 + lane];
            acc0 = fmaf(p, vv.x, acc0);
            acc1 = fmaf(p, vv.y, acc1);
        }
        __syncthreads();
    }

    // ---- epilogue: invert frame on o_pt, norms, write cat ----
    if (lane >= 16) optbuf[warp][lane-16]  = acc0;   // dims 16..31
    if (lane <  8)  optbuf[warp][16+lane]  = acc1;   // dims 32..39
    __syncwarp();
    if (lane < 16) g_cat[i*576 + h*CH + lane] = acc0;
    if (lane < 8) {
        int p = lane;
        float ox = optbuf[warp][p*3+0] - t_dst[i*3+0];
        float oy = optbuf[warp][p*3+1] - t_dst[i*3+1];
        float oz = optbuf[warp][p*3+2] - t_dst[i*3+2];
        const float* R = R_dst + i*9;
        float lx = R[0]*ox + R[3]*oy + R[6]*oz;   // R^T
        float ly = R[1]*ox + R[4]*oy + R[7]*oz;
        float lz = R[2]*ox + R[5]*oy + R[8]*oz;
        float nrm = sqrtf(lx*lx + ly*ly + lz*lz + 1e-8f);
        float* cat = g_cat + i*576 + 192;
        cat[        h*PV + p] = lx;
        cat[ 96 +   h*PV + p] = ly;
        cat[192 +   h*PV + p] = lz;
        cat[288 +   h*PV + p] = nrm;
    }
}

// ---------------- launch ----------------
extern "C" void kernel_launch(void* const* d_in, const int* in_sizes, int n_in,
                              void* d_out, int out_size) {
    const float* s_dst    = (const float*)d_in[0];
    const float* s_src    = (const float*)d_in[1];
    const float* R_dst    = (const float*)d_in[2];
    const float* t_dst    = (const float*)d_in[3];
    const float* R_src    = (const float*)d_in[4];
    const float* t_src    = (const float*)d_in[5];
    const float* dst_mask = (const float*)d_in[6];
    const float* src_mask = (const float*)d_in[7];
    const float* W_q      = (const float*)d_in[8];
    const float* W_kv     = (const float*)d_in[9];
    const float* W_qp     = (const float*)d_in[10];
    const float* W_kvp    = (const float*)d_in[11];
    const float* W_out    = (const float*)d_in[12];
    const float* b_out    = (const float*)d_in[13];
    const float* head_w   = (const float*)d_in[14];

    float* out     = (float*)d_out;
    float* s_upd   = out;
    float* a_out   = out + (long long)LDQ*CS;
    float* asd_out = a_out + (long long)NH*LDQ*LSK;
    float* apts_out= asd_out + (long long)NH*LDQ*LSK;

    float *pq, *pqpraw, *pkv, *pkvpraw, *pcat;
    cudaGetSymbolAddress((void**)&pq,      g_q);
    cudaGetSymbolAddress((void**)&pqpraw,  g_qp_raw);
    cudaGetSymbolAddress((void**)&pkv,     g_kv);
    cudaGetSymbolAddress((void**)&pkvpraw, g_kvp_raw);
    cudaGetSymbolAddress((void**)&pcat,    g_cat);

    // projections
    gemm_bias<<<dim3(3, 8),  256>>>(s_dst, W_q,   pq,      LDQ, NH*CH,        CS, nullptr);
    gemm_bias<<<dim3(3, 8),  256>>>(s_dst, W_qp,  pqpraw,  LDQ, NH*PQ*3,      CS, nullptr);
    gemm_bias<<<dim3(6, 32), 256>>>(s_src, W_kv,  pkv,     LSK, 2*NH*CH,      CS, nullptr);
    gemm_bias<<<dim3(7, 32), 256>>>(s_src, W_kvp, pkvpraw, LSK, NH*(PQ+PV)*3, CS, nullptr);

    // apply frames
    rot_dst_kernel<<<(LDQ*48  + 255)/256, 256>>>(R_dst, t_dst);
    rot_src_kernel<<<(LSK*144 + 255)/256, 256>>>(R_src, t_src);

    // attention
    size_t shbytes = (size_t)TI*LSK*4 + (size_t)64*33*8;   // 65536 + 16896 = 82432
    cudaFuncSetAttribute(attn_kernel, cudaFuncAttributeMaxDynamicSharedMemorySize, (int)shbytes);
    attn_kernel<<<dim3(NH, LDQ/TI), 256, shbytes>>>(dst_mask, src_mask, R_dst, t_dst, head_w,
                                                    a_out, asd_out, apts_out);

    // output projection
    gemm_bias<<<dim3(6, 8), 256>>>(pcat, W_out, s_upd, LDQ, CS, 576, b_out);
}

// round 2
// speedup vs baseline: 2.6010x; 2.6010x over previous
#include <cuda_runtime.h>
#include <math.h>

#define LDQ 512
#define LSK 2048
#define CS  384
#define NH  12

// ---------------- scratch ----------------
__device__ float g_q[LDQ*192];
__device__ float g_qp_raw[LDQ*144];
__device__ float g_kv[LSK*384];
__device__ float g_kvp_raw[LSK*432];
__device__ float g_qaug[NH*LDQ*32];
__device__ float g_kaug[NH*LSK*32];
__device__ float g_pv[NH*LSK*40];
__device__ float g_opart[4*NH*LDQ*40];
__device__ float g_cat[LDQ*576];

// ---------------- generic 32x64 tile GEMM (128 threads, 4x4 microtile) ----------------
__device__ __forceinline__ void gemm_32x64(
    const float* __restrict__ A, const float* __restrict__ B, float* __restrict__ C,
    int M, int N, int K, const float* __restrict__ bias)
{
    __shared__ float As[16][33];
    __shared__ float Bs[16][64];
    const int t  = threadIdx.x;
    const int tx = t & 15;        // n-group (16 x 4 = 64)
    const int ty = t >> 4;        // m-group (8 x 4 = 32)
    const int m0 = blockIdx.y * 32;
    const int n0 = blockIdx.x * 64;
    float acc[4][4] = {};

    for (int kt = 0; kt < K; kt += 16) {
#pragma unroll
        for (int u = 0; u < 4; u++) {
            int idx = t + 128*u; int m = idx >> 4, k = idx & 15;
            As[k][m] = A[(m0 + m)*K + kt + k];
        }
#pragma unroll
        for (int u = 0; u < 8; u++) {
            int idx = t + 128*u; int k = idx >> 6, n = idx & 63;
            int gn = n0 + n;
            Bs[k][n] = (gn < N) ? B[(kt + k)*N + gn] : 0.f;
        }
        __syncthreads();
#pragma unroll
        for (int kk = 0; kk < 16; kk++) {
            float a0[4], b0[4];
#pragma unroll
            for (int i = 0; i < 4; i++) a0[i] = As[kk][ty*4 + i];
#pragma unroll
            for (int j = 0; j < 4; j++) b0[j] = Bs[kk][tx*4 + j];
#pragma unroll
            for (int i = 0; i < 4; i++)
#pragma unroll
                for (int j = 0; j < 4; j++)
                    acc[i][j] = fmaf(a0[i], b0[j], acc[i][j]);
        }
        __syncthreads();
    }
#pragma unroll
    for (int i = 0; i < 4; i++) {
        int gm = m0 + ty*4 + i;
#pragma unroll
        for (int j = 0; j < 4; j++) {
            int gn = n0 + tx*4 + j;
            if (gn < N) C[gm*N + gn] = acc[i][j] + (bias ? bias[gn] : 0.f);
        }
    }
}

// fused 4-way projection: z selects which GEMM
__global__ __launch_bounds__(128) void proj_all(
    const float* __restrict__ s_dst, const float* __restrict__ s_src,
    const float* __restrict__ Wq, const float* __restrict__ Wqp,
    const float* __restrict__ Wkv, const float* __restrict__ Wkvp)
{
    const float* A; const float* B; float* C; int M, N;
    switch (blockIdx.z) {
        case 0:  A = s_dst; B = Wq;   C = g_q;       M = LDQ; N = 192; break;
        case 1:  A = s_dst; B = Wqp;  C = g_qp_raw;  M = LDQ; N = 144; break;
        case 2:  A = s_src; B = Wkv;  C = g_kv;      M = LSK; N = 384; break;
        default: A = s_src; B = Wkvp; C = g_kvp_raw; M = LSK; N = 432; break;
    }
    if ((int)blockIdx.x*64 >= N || (int)blockIdx.y*32 >= M) return;
    gemm_32x64(A, B, C, M, N, CS, nullptr);
}

__global__ __launch_bounds__(128) void out_gemm(
    const float* __restrict__ Wout, const float* __restrict__ bout, float* __restrict__ s_upd)
{
    gemm_32x64(g_cat, Wout, s_upd, LDQ, 384, 576, bout);
}

// ---------------- augmentation (fused frame application) ----------------
__global__ void augq_kernel(const float* __restrict__ R_dst, const float* __restrict__ t_dst,
                            const float* __restrict__ head_w)
{
    int idx = blockIdx.x*256 + threadIdx.x;
    if (idx >= LDQ*NH) return;
    int i = idx / NH, h = idx - (idx/NH)*NH;
    float hw = log1pf(__expf(head_w[h])) * (1.0f/6.0f);
    const float qksc = 0.17677669529663689f;
    float* outp = &g_qaug[(h*LDQ + i)*32];
#pragma unroll
    for (int c = 0; c < 16; c++) outp[c] = g_q[i*192 + h*16 + c] * qksc;
    const float* R = R_dst + i*9; const float* tv = t_dst + i*3;
    float s2 = 0.f;
#pragma unroll
    for (int p = 0; p < 4; p++) {
        float l0 = g_qp_raw[i*144 +       h*4 + p];
        float l1 = g_qp_raw[i*144 + 48  + h*4 + p];
        float l2 = g_qp_raw[i*144 + 96  + h*4 + p];
        float gx = R[0]*l0 + R[1]*l1 + R[2]*l2 + tv[0];
        float gy = R[3]*l0 + R[4]*l1 + R[5]*l2 + tv[1];
        float gz = R[6]*l0 + R[7]*l1 + R[8]*l2 + tv[2];
        outp[16 + p*3 + 0] = hw*gx;
        outp[16 + p*3 + 1] = hw*gy;
        outp[16 + p*3 + 2] = hw*gz;
        s2 = fmaf(gx, gx, fmaf(gy, gy, fmaf(gz, gz, s2)));
    }
    outp[28] = -0.5f*hw*s2; outp[29] = 1.f; outp[30] = 0.f; outp[31] = 0.f;
}

__global__ void augk_kernel(const float* __restrict__ R_src, const float* __restrict__ t_src,
                            const float* __restrict__ head_w)
{
    int idx = blockIdx.x*256 + threadIdx.x;
    if (idx >= LSK*NH) return;
    int j = idx / NH, h = idx - (idx/NH)*NH;
    float hw = log1pf(__expf(head_w[h])) * (1.0f/6.0f);
    float* kout = &g_kaug[(h*LSK + j)*32];
#pragma unroll
    for (int c = 0; c < 16; c++) kout[c] = g_kv[j*384 + h*32 + c];
    const float* R = R_src + j*9; const float* tv = t_src + j*3;
    float s2 = 0.f;
#pragma unroll
    for (int pp = 0; pp < 4; pp++) {
        float l0 = g_kvp_raw[j*432 +        h*12 + pp];
        float l1 = g_kvp_raw[j*432 + 144 +  h*12 + pp];
        float l2 = g_kvp_raw[j*432 + 288 +  h*12 + pp];
        float gx = R[0]*l0 + R[1]*l1 + R[2]*l2 + tv[0];
        float gy = R[3]*l0 + R[4]*l1 + R[5]*l2 + tv[1];
        float gz = R[6]*l0 + R[7]*l1 + R[8]*l2 + tv[2];
        kout[16 + pp*3 + 0] = gx;
        kout[16 + pp*3 + 1] = gy;
        kout[16 + pp*3 + 2] = gz;
        s2 = fmaf(gx, gx, fmaf(gy, gy, fmaf(gz, gz, s2)));
    }
    kout[28] = 1.f; kout[29] = -0.5f*hw*s2; kout[30] = 0.f; kout[31] = 0.f;
    float* pv = &g_pv[(h*LSK + j)*40];
#pragma unroll
    for (int c = 0; c < 16; c++) pv[c] = g_kv[j*384 + h*32 + 16 + c];
#pragma unroll
    for (int pp = 4; pp < 12; pp++) {
        float l0 = g_kvp_raw[j*432 +        h*12 + pp];
        float l1 = g_kvp_raw[j*432 + 144 +  h*12 + pp];
        float l2 = g_kvp_raw[j*432 + 288 +  h*12 + pp];
        pv[16 + (pp-4)*3 + 0] = R[0]*l0 + R[1]*l1 + R[2]*l2 + tv[0];
        pv[16 + (pp-4)*3 + 1] = R[3]*l0 + R[4]*l1 + R[5]*l2 + tv[1];
        pv[16 + (pp-4)*3 + 2] = R[6]*l0 + R[7]*l1 + R[8]*l2 + tv[2];
    }
}

// ---------------- logits: 64x64 tile GEMM over 32 dims, dual accumulators ----------------
__global__ __launch_bounds__(256) void logits_kernel(
    const float* __restrict__ dst_mask, const float* __restrict__ src_mask,
    float* __restrict__ a_out, float* __restrict__ asd_out, float* __restrict__ apts_out)
{
    __shared__ float As[32][65];
    __shared__ float Bs[32][65];
    __shared__ float dmt[64], smt[64];
    const int h  = blockIdx.z;
    const int i0 = blockIdx.y * 64;
    const int j0 = blockIdx.x * 64;
    const int t  = threadIdx.x;
    const int tx = t & 15, ty = t >> 4;

#pragma unroll
    for (int u = 0; u < 8; u++) {
        int idx = t + 256*u; int m = idx >> 5, c = idx & 31;
        As[c][m] = g_qaug[(h*LDQ + i0 + m)*32 + c];
        Bs[c][m] = g_kaug[(h*LSK + j0 + m)*32 + c];
    }
    if (t < 64) { dmt[t] = dst_mask[i0 + t]; smt[t] = src_mask[j0 + t]; }
    __syncthreads();

    float accA[4][4] = {}, accB[4][4] = {};
#pragma unroll 4
    for (int kk = 0; kk < 16; kk++) {
        float a0[4], b0[4];
#pragma unroll
        for (int i = 0; i < 4; i++) a0[i] = As[kk][ty*4 + i];
#pragma unroll
        for (int j = 0; j < 4; j++) b0[j] = Bs[kk][tx*4 + j];
#pragma unroll
        for (int i = 0; i < 4; i++)
#pragma unroll
            for (int j = 0; j < 4; j++)
                accA[i][j] = fmaf(a0[i], b0[j], accA[i][j]);
    }
#pragma unroll 4
    for (int kk = 16; kk < 32; kk++) {
        float a0[4], b0[4];
#pragma unroll
        for (int i = 0; i < 4; i++) a0[i] = As[kk][ty*4 + i];
#pragma unroll
        for (int j = 0; j < 4; j++) b0[j] = Bs[kk][tx*4 + j];
#pragma unroll
        for (int i = 0; i < 4; i++)
#pragma unroll
            for (int j = 0; j < 4; j++)
                accB[i][j] = fmaf(a0[i], b0[j], accB[i][j]);
    }

#pragma unroll
    for (int i = 0; i < 4; i++) {
        int gi = i0 + ty*4 + i;
        float dm = dmt[ty*4 + i];
#pragma unroll
        for (int j = 0; j < 4; j++) {
            int gj = j0 + tx*4 + j;
            float g = dm * smt[tx*4 + j];
            int off = (h*LDQ + gi)*LSK + gj;
            asd_out[off]  = accA[i][j] * g;
            apts_out[off] = accB[i][j] * g;
            a_out[off]    = accA[i][j] + accB[i][j] + 1e9f*(g - 1.f);
        }
    }
}

// ---------------- softmax over each (h,i) row of 2048, in-place on a_out ----------------
__global__ __launch_bounds__(256) void softmax_kernel(float* __restrict__ a_out)
{
    const int row = blockIdx.x;                 // 0..NH*LDQ-1
    float* p = a_out + (size_t)row * LSK;
    const int t = threadIdx.x;
    float4 v0 = ((const float4*)p)[t];
    float4 v1 = ((const float4*)p)[t + 256];

    float m = fmaxf(fmaxf(fmaxf(v0.x, v0.y), fmaxf(v0.z, v0.w)),
                    fmaxf(fmaxf(v1.x, v1.y), fmaxf(v1.z, v1.w)));
    __shared__ float red[8];
    __shared__ float bcast;
#pragma unroll
    for (int o = 16; o; o >>= 1) m = fmaxf(m, __shfl_xor_sync(0xffffffffu, m, o));
    if ((t & 31) == 0) red[t >> 5] = m;
    __syncthreads();
    if (t < 8) {
        float mm = red[t];
#pragma unroll
        for (int o = 4; o; o >>= 1) mm = fmaxf(mm, __shfl_xor_sync(0xffu, mm, o));
        if (t == 0) bcast = mm;
    }
    __syncthreads();
    m = bcast;

    v0.x = __expf(v0.x - m); v0.y = __expf(v0.y - m);
    v0.z = __expf(v0.z - m); v0.w = __expf(v0.w - m);
    v1.x = __expf(v1.x - m); v1.y = __expf(v1.y - m);
    v1.z = __expf(v1.z - m); v1.w = __expf(v1.w - m);
    float s = v0.x + v0.y + v0.z + v0.w + v1.x + v1.y + v1.z + v1.w;
#pragma unroll
    for (int o = 16; o; o >>= 1) s += __shfl_xor_sync(0xffffffffu, s, o);
    __syncthreads();
    if ((t & 31) == 0) red[t >> 5] = s;
    __syncthreads();
    if (t < 8) {
        float ss = red[t];
#pragma unroll
        for (int o = 4; o; o >>= 1) ss += __shfl_xor_sync(0xffu, ss, o);
        if (t == 0) bcast = ss;
    }
    __syncthreads();
    float inv = 1.f / bcast;
    v0.x *= inv; v0.y *= inv; v0.z *= inv; v0.w *= inv;
    v1.x *= inv; v1.y *= inv; v1.z *= inv; v1.w *= inv;
    ((float4*)p)[t]       = v0;
    ((float4*)p)[t + 256] = v1;
}

// ---------------- AV: 64i x 40d tile, j split 4-way deterministic ----------------
__global__ __launch_bounds__(128) void av_kernel(const float* __restrict__ a_out)
{
    __shared__ float Ps[32][65];
    __shared__ float Vs[32][40];
    const int jq = blockIdx.x;          // 0..3
    const int i0 = blockIdx.y * 64;
    const int h  = blockIdx.z;
    const int t  = threadIdx.x;
    const int tx = t & 7;               // d-group (8 x 5 = 40)
    const int ty = t >> 3;              // i-group (16 x 4 = 64)
    const int jbase = jq * 512;
    float acc[4][5] = {};

    for (int jt = 0; jt < 512; jt += 32) {
#pragma unroll
        for (int u = 0; u < 16; u++) {
            int idx = t + 128*u; int i = idx >> 5, j = idx & 31;
            Ps[j][i] = a_out[(h*LDQ + i0 + i)*LSK + jbase + jt + j];
        }
#pragma unroll
        for (int u = 0; u < 10; u++) {
            int idx = t + 128*u; int j = idx / 40, d = idx - j*40;
            Vs[j][d] = g_pv[(h*LSK + jbase + jt + j)*40 + d];
        }
        __syncthreads();
#pragma unroll 4
        for (int kk = 0; kk < 32; kk++) {
            float pr[4], vv[5];
#pragma unroll
            for (int i = 0; i < 4; i++) pr[i] = Ps[kk][ty*4 + i];
#pragma unroll
            for (int d = 0; d < 5; d++) vv[d] = Vs[kk][tx*5 + d];
#pragma unroll
            for (int i = 0; i < 4; i++)
#pragma unroll
                for (int d = 0; d < 5; d++)
                    acc[i][d] = fmaf(pr[i], vv[d], acc[i][d]);
        }
        __syncthreads();
    }
#pragma unroll
    for (int i = 0; i < 4; i++)
#pragma unroll
        for (int d = 0; d < 5; d++)
            g_opart[((jq*NH + h)*LDQ + i0 + ty*4 + i)*40 + tx*5 + d] = acc[i][d];
}

// ---------------- epilogue: reduce partials, invert frame, norms, build cat ----------------
__global__ void epilogue_kernel(const float* __restrict__ R_dst, const float* __restrict__ t_dst)
{
    const int i = blockIdx.x;
    const int t = threadIdx.x;           // 288 threads
    if (t < 192) {
        int h = t >> 4, c = t & 15;
        float s = 0.f;
#pragma unroll
        for (int q = 0; q < 4; q++) s += g_opart[((q*NH + h)*LDQ + i)*40 + c];
        g_cat[i*576 + t] = s;
    } else if (t < 288) {
        int pt = t - 192;
        int h = pt >> 3, p = pt & 7;
        int d = 16 + p*3;
        float ox = 0.f, oy = 0.f, oz = 0.f;
#pragma unroll
        for (int q = 0; q < 4; q++) {
            int base = ((q*NH + h)*LDQ + i)*40 + d;
            ox += g_opart[base];
            oy += g_opart[base + 1];
            oz += g_opart[base + 2];
        }
        ox -= t_dst[i*3 + 0]; oy -= t_dst[i*3 + 1]; oz -= t_dst[i*3 + 2];
        const float* R = R_dst + i*9;
        float lx = R[0]*ox + R[3]*oy + R[6]*oz;
        float ly = R[1]*ox + R[4]*oy + R[7]*oz;
        float lz = R[2]*ox + R[5]*oy + R[8]*oz;
        float nrm = sqrtf(lx*lx + ly*ly + lz*lz + 1e-8f);
        float* cat = g_cat + i*576 + 192;
        cat[        pt] = lx;
        cat[ 96 +   pt] = ly;
        cat[192 +   pt] = lz;
        cat[288 +   pt] = nrm;
    }
}

// ---------------- launch ----------------
extern "C" void kernel_launch(void* const* d_in, const int* in_sizes, int n_in,
                              void* d_out, int out_size) {
    const float* s_dst    = (const float*)d_in[0];
    const float* s_src    = (const float*)d_in[1];
    const float* R_dst    = (const float*)d_in[2];
    const float* t_dst    = (const float*)d_in[3];
    const float* R_src    = (const float*)d_in[4];
    const float* t_src    = (const float*)d_in[5];
    const float* dst_mask = (const float*)d_in[6];
    const float* src_mask = (const float*)d_in[7];
    const float* W_q      = (const float*)d_in[8];
    const float* W_kv     = (const float*)d_in[9];
    const float* W_qp     = (const float*)d_in[10];
    const float* W_kvp    = (const float*)d_in[11];
    const float* W_out    = (const float*)d_in[12];
    const float* b_out    = (const float*)d_in[13];
    const float* head_w   = (const float*)d_in[14];

    float* out      = (float*)d_out;
    float* s_upd    = out;
    float* a_out    = out + (long long)LDQ*CS;
    float* asd_out  = a_out  + (long long)NH*LDQ*LSK;
    float* apts_out = asd_out + (long long)NH*LDQ*LSK;

    proj_all<<<dim3(7, 64, 4), 128>>>(s_dst, s_src, W_q, W_qp, W_kv, W_kvp);
    augq_kernel<<<(LDQ*NH + 255)/256, 256>>>(R_dst, t_dst, head_w);
    augk_kernel<<<(LSK*NH + 255)/256, 256>>>(R_src, t_src, head_w);
    logits_kernel<<<dim3(32, 8, 12), 256>>>(dst_mask, src_mask, a_out, asd_out, apts_out);
    softmax_kernel<<<NH*LDQ, 256>>>(a_out);
    av_kernel<<<dim3(4, 8, 12), 128>>>(a_out);
    epilogue_kernel<<<LDQ, 288>>>(R_dst, t_dst);
    out_gemm<<<dim3(6, 16), 128>>>(W_out, b_out, s_upd);
}